// round 10
// baseline (speedup 1.0000x reference)
#include <cuda_runtime.h>
#include <cstdint>

// Problem shapes
#define B_ 128
#define S_ 37
#define T_ 2048
#define D_ 256
#define ST_ 8
#define C_ 2
#define MERGED_ 264
#define NF (2*S_)          // 74 features (x ++ mask)
#define TC 128             // time chunk per CTA
#define NCHUNK (T_/TC)     // 16

#define G2 2               // batches per stage2 CTA -> 64 CTAs
#define NTHR2 528          // stage2 threads (G2*MERGED_)
#define TILE_K 66          // Wm k-tile rows (264 = 4*66)
#define NTILE 4
#define SLOT (NF * D_)     // 18944 floats: fits Ws whole, and any Wm tile (17424)

// Per-chunk partial reductions (written without atomics -> deterministic)
__device__ float g_px[(size_t)NCHUNK * B_ * NF];
__device__ float g_pm[NCHUNK * B_];
__device__ float g_pt[NCHUNK * B_];

__device__ __forceinline__ float wred(float v) {
#pragma unroll
    for (int o = 16; o > 0; o >>= 1) v += __shfl_xor_sync(0xffffffffu, v, o);
    return v;
}

__device__ __forceinline__ uint32_t smem_u32(const void* p) {
    return (uint32_t)__cvta_generic_to_shared(p);
}
__device__ __forceinline__ void cpa16(uint32_t s, const void* g) {
    asm volatile("cp.async.cg.shared.global [%0], [%1], 16;" :: "r"(s), "l"(g));
}
__device__ __forceinline__ void cpa_commit() {
    asm volatile("cp.async.commit_group;" ::: "memory");
}
template <int N>
__device__ __forceinline__ void cpa_wait() {
    asm volatile("cp.async.wait_group %0;" :: "n"(N) : "memory");
}

// ---------------------------------------------------------------------------
// Stage 1: HBM/L2-roofline pass over x + sensor_mask (77.6 MB).
// ---------------------------------------------------------------------------
__global__ __launch_bounds__(256) void stage1(const float* __restrict__ x,
                                              const int*   __restrict__ smk,
                                              const float* __restrict__ tm) {
    __shared__ float xs[S_ * TC];
    __shared__ int   msi[S_ * TC];
    __shared__ float valid[TC];
    __shared__ float red[8][2];

    const int chunk = blockIdx.x;
    const int b     = blockIdx.y;
    const int t0    = chunk * TC;

    const float* xb = x   + (size_t)b * S_ * T_ + t0;
    const int*   mb = smk + (size_t)b * S_ * T_ + t0;

    for (int idx = threadIdx.x; idx < S_ * (TC / 4); idx += 256) {
        int s = idx / (TC / 4);
        int j = (idx % (TC / 4)) * 4;
        float4 v = *(const float4*)(xb + (size_t)s * T_ + j);
        *(float4*)(xs + s * TC + j) = v;
        int4 m = *(const int4*)(mb + (size_t)s * T_ + j);
        *(int4*)(msi + s * TC + j) = m;
    }
    __syncthreads();

    float vf = 0.f, tv = 0.f;
    if (threadIdx.x < TC) {
        const int t = threadIdx.x;
        int nz = 0;
#pragma unroll
        for (int s = 0; s < S_; s++) {
            nz |= (xs[s * TC + t] != 0.f);
            nz |= (msi[s * TC + t] != 0);
        }
        vf = nz ? 1.f : 0.f;
        valid[t] = vf;
        tv = vf * tm[(size_t)b * T_ + t0 + t];
    }

    const int w = threadIdx.x >> 5, lane = threadIdx.x & 31;
    float rv = wred(vf), rt = wred(tv);
    if (lane == 0) { red[w][0] = rv; red[w][1] = rt; }
    __syncthreads();
    if (threadIdx.x == 0) {
        float a = 0.f, c = 0.f;
#pragma unroll
        for (int i = 0; i < 8; i++) { a += red[i][0]; c += red[i][1]; }
        g_pm[chunk * B_ + b] = a;
        g_pt[chunk * B_ + b] = c;
    }

    for (int f = w; f < NF; f += 8) {
        float p = 0.f;
        if (f < S_) {
            const float* src = xs + f * TC;
#pragma unroll
            for (int j = lane; j < TC; j += 32) p += valid[j] * src[j];
        } else {
            const int* src = msi + (f - S_) * TC;
#pragma unroll
            for (int j = lane; j < TC; j += 32) p += valid[j] * (float)src[j];
        }
        p = wred(p);
        if (lane == 0) g_px[((size_t)chunk * B_ + b) * NF + f] = p;
    }
}

// ---------------------------------------------------------------------------
// Stage 2: 64 CTAs x 528 threads; G2=2 batches per CTA. Ws and Wm streamed
// through smem via cp.async (double-buffered Wm tiles); compute is LDS+FFMA.
// Tile j lives in slot (j+1)&1  (tile0 -> slot1, since slot0 holds Ws first).
// ---------------------------------------------------------------------------
__global__ __launch_bounds__(NTHR2) void stage2(
    const float* __restrict__ stat,
    const float* __restrict__ Ws,  const float* __restrict__ bs,
    const float* __restrict__ Wt,  const float* __restrict__ bt,
    const float* __restrict__ Wst, const float* __restrict__ bst,
    const float* __restrict__ Wm,  const float* __restrict__ bm,
    const float* __restrict__ Wc,  const float* __restrict__ bc,
    float* __restrict__ out) {
    extern __shared__ __align__(16) float buf[];   // 2 slots of SLOT floats
    __shared__ float xpart[3][G2][NF];
    __shared__ float xsum[G2][NF];
    __shared__ float comb[G2][MERGED_];
    __shared__ float comb2[G2][MERGED_];
    __shared__ float sden[G2][2];

    const int b0  = blockIdx.x * G2;
    const int tid = threadIdx.x;
    float* slot0 = buf;
    float* slot1 = buf + SLOT;

    // ---- issue Ws -> slot0 (group A) -------------------------------------
    {
        const float4* src = (const float4*)Ws;
        uint32_t dst = smem_u32(slot0);
        for (int i = tid; i < SLOT / 4; i += NTHR2)
            cpa16(dst + 16u * i, src + i);
        cpa_commit();
    }

    // ---- xsum partials (j-split 3-way, chain depth <= 6) ------------------
    if (tid < 3 * G2 * NF) {
        const int j = tid / (G2 * NF);
        const int r = tid % (G2 * NF);
        const int g = r / NF, f = r % NF;
        float a = 0.f;
        for (int c = j; c < NCHUNK; c += 3)
            a += g_px[((size_t)c * B_ + (b0 + g)) * NF + f];
        xpart[j][g][f] = a;
    }
    if (tid >= 448 && tid < 448 + G2) {
        const int g = tid - 448;
        float a = 0.f, t = 0.f;
#pragma unroll
        for (int c = 0; c < NCHUNK; c++) {
            a += g_pm[c * B_ + b0 + g];
            t += g_pt[c * B_ + b0 + g];
        }
        float den = fmaxf(a, 1e-9f);
        sden[g][0] = den;
        sden[g][1] = t / den;
    }
    // static embedding on spare threads
    if (tid >= 512) {
        const int j = tid - 512;       // 0..15
        const int g = j / ST_, jj = j % ST_;
        float p = bst[jj];
#pragma unroll
        for (int i = 0; i < ST_; i++)
            p += stat[(b0 + g) * ST_ + i] * Wst[i * ST_ + jj];
        comb[g][D_ + jj] = p;
    }

    cpa_wait<0>();          // Ws resident
    __syncthreads();

    if (tid < G2 * NF) {    // combine xsum partials
        const int g = tid / NF, f = tid % NF;
        xsum[g][f] = xpart[0][g][f] + xpart[1][g][f] + xpart[2][g][f];
    }
    __syncthreads();

    // ---- issue Wm tile0 -> slot1 (group B), then projection from slot0 ----
    {
        const float4* src = (const float4*)Wm;
        uint32_t dst = smem_u32(slot1);
        for (int i = tid; i < TILE_K * MERGED_ / 4; i += NTHR2)
            cpa16(dst + 16u * i, src + i);
        cpa_commit();
    }

    if (tid < G2 * D_) {
        const int g = tid / D_, d = tid % D_;
        float a0 = 0.f, a1 = 0.f;
#pragma unroll 2
        for (int k = 0; k < NF; k += 2) {
            a0 += xsum[g][k]     * slot0[k * D_ + d];
            a1 += xsum[g][k + 1] * slot0[(k + 1) * D_ + d];
        }
        const float den = sden[g][0], tsc = sden[g][1];
        comb[g][d] = (a0 + a1) / den + bs[d] + bt[d] + tsc * Wt[d];
    }
    __syncthreads();        // comb complete; slot0 free for tile1

    // ---- merge: 4 double-buffered Wm tiles (tile j in slot (j+1)&1) -------
    const int gm = tid / MERGED_;           // 0,1
    const int n  = tid % MERGED_;
    float acc = 0.f;
#pragma unroll
    for (int t = 0; t < NTILE; t++) {
        // issue tile t+1 into slot ((t+1)+1)&1 == t&1
        if (t + 1 < NTILE) {
            const float4* src = (const float4*)(Wm + (size_t)(t + 1) * TILE_K * MERGED_);
            uint32_t dst = smem_u32((t & 1) ? slot1 : slot0);
            for (int i = tid; i < TILE_K * MERGED_ / 4; i += NTHR2)
                cpa16(dst + 16u * i, src + i);
            cpa_commit();
            cpa_wait<1>();  // tile t ready (only the newest group pending)
        } else {
            cpa_wait<0>();
        }
        __syncthreads();
        const float* wm_s = (((t + 1) & 1) ? slot1 : slot0);   // tile t
        const float* cb = &comb[gm][t * TILE_K];
#pragma unroll 2
        for (int kk = 0; kk < TILE_K; kk += 2) {
            acc += cb[kk]     * wm_s[kk * MERGED_ + n];
            acc += cb[kk + 1] * wm_s[(kk + 1) * MERGED_ + n];
        }
        __syncthreads();    // done reading this slot before it is refilled
    }
    comb2[gm][n] = fmaxf(acc + bm[n], 0.f);
    __syncthreads();

    // ---- classifier: 4 (g,c) jobs on warps 0..3 --------------------------
    const int w = tid >> 5, lane = tid & 31;
    if (w < G2 * C_) {
        const int g = w >> 1, c = w & 1;
        float p = 0.f;
#pragma unroll
        for (int i = lane; i < MERGED_; i += 32) p += comb2[g][i] * Wc[i * C_ + c];
        p = wred(p);
        if (lane == 0) out[(b0 + g) * C_ + c] = p + bc[c];
    }
}

extern "C" void kernel_launch(void* const* d_in, const int* in_sizes, int n_in,
                              void* d_out, int out_size) {
    const float* x   = (const float*)d_in[0];
    const float* st  = (const float*)d_in[1];
    const float* tm  = (const float*)d_in[2];
    const int*   smk = (const int*)  d_in[3];
    const float* Ws  = (const float*)d_in[4];
    const float* bs  = (const float*)d_in[5];
    const float* Wt  = (const float*)d_in[6];
    const float* bt  = (const float*)d_in[7];
    const float* Wst = (const float*)d_in[8];
    const float* bst = (const float*)d_in[9];
    const float* Wm  = (const float*)d_in[10];
    const float* bm  = (const float*)d_in[11];
    const float* Wc  = (const float*)d_in[12];
    const float* bc  = (const float*)d_in[13];

    static bool attr_set = false;
    const int dsmem = 2 * SLOT * sizeof(float);   // 151552 B
    if (!attr_set) {
        cudaFuncSetAttribute(stage2, cudaFuncAttributeMaxDynamicSharedMemorySize,
                             dsmem);
        attr_set = true;
    }

    stage1<<<dim3(NCHUNK, B_), 256>>>(x, smk, tm);
    stage2<<<B_ / G2, NTHR2, dsmem>>>(st, Ws, bs, Wt, bt, Wst, bst,
                                      Wm, bm, Wc, bc, (float*)d_out);
}

// round 11
// speedup vs baseline: 1.1979x; 1.1979x over previous
#include <cuda_runtime.h>
#include <cstdint>

// Problem shapes
#define B_ 128
#define S_ 37
#define T_ 2048
#define D_ 256
#define ST_ 8
#define C_ 2
#define MERGED_ 264
#define NF (2*S_)          // 74 features (x ++ mask)
#define TC 128             // time chunk per CTA
#define NCHUNK (T_/TC)     // 16

#define NTHR2 528          // stage2 threads

// Per-chunk partial reductions (written without atomics -> deterministic)
__device__ float g_px[(size_t)NCHUNK * B_ * NF];
__device__ float g_pm[NCHUNK * B_];
__device__ float g_pt[NCHUNK * B_];

__device__ __forceinline__ float wred(float v) {
#pragma unroll
    for (int o = 16; o > 0; o >>= 1) v += __shfl_xor_sync(0xffffffffu, v, o);
    return v;
}

// ---------------------------------------------------------------------------
// Stage 1: HBM/L2-roofline pass over x + sensor_mask (77.6 MB).
// ---------------------------------------------------------------------------
__global__ __launch_bounds__(256) void stage1(const float* __restrict__ x,
                                              const int*   __restrict__ smk,
                                              const float* __restrict__ tm) {
    __shared__ float xs[S_ * TC];
    __shared__ int   msi[S_ * TC];
    __shared__ float valid[TC];
    __shared__ float red[8][2];

    const int chunk = blockIdx.x;
    const int b     = blockIdx.y;
    const int t0    = chunk * TC;

    const float* xb = x   + (size_t)b * S_ * T_ + t0;
    const int*   mb = smk + (size_t)b * S_ * T_ + t0;

    for (int idx = threadIdx.x; idx < S_ * (TC / 4); idx += 256) {
        int s = idx / (TC / 4);
        int j = (idx % (TC / 4)) * 4;
        float4 v = *(const float4*)(xb + (size_t)s * T_ + j);
        *(float4*)(xs + s * TC + j) = v;
        int4 m = *(const int4*)(mb + (size_t)s * T_ + j);
        *(int4*)(msi + s * TC + j) = m;
    }
    __syncthreads();

    float vf = 0.f, tv = 0.f;
    if (threadIdx.x < TC) {
        const int t = threadIdx.x;
        int nz = 0;
#pragma unroll
        for (int s = 0; s < S_; s++) {
            nz |= (xs[s * TC + t] != 0.f);
            nz |= (msi[s * TC + t] != 0);
        }
        vf = nz ? 1.f : 0.f;
        valid[t] = vf;
        tv = vf * tm[(size_t)b * T_ + t0 + t];
    }

    const int w = threadIdx.x >> 5, lane = threadIdx.x & 31;
    float rv = wred(vf), rt = wred(tv);
    if (lane == 0) { red[w][0] = rv; red[w][1] = rt; }
    __syncthreads();
    if (threadIdx.x == 0) {
        float a = 0.f, c = 0.f;
#pragma unroll
        for (int i = 0; i < 8; i++) { a += red[i][0]; c += red[i][1]; }
        g_pm[chunk * B_ + b] = a;
        g_pt[chunk * B_ + b] = c;
    }

    for (int f = w; f < NF; f += 8) {
        float p = 0.f;
        if (f < S_) {
            const float* src = xs + f * TC;
#pragma unroll
            for (int j = lane; j < TC; j += 32) p += valid[j] * src[j];
        } else {
            const int* src = msi + (f - S_) * TC;
#pragma unroll
            for (int j = lane; j < TC; j += 32) p += valid[j] * (float)src[j];
        }
        p = wred(p);
        if (lane == 0) g_px[((size_t)chunk * B_ + b) * NF + f] = p;
    }
}

// ---------------------------------------------------------------------------
// Stage 2: one CTA per batch (128 CTAs x 528 threads). Every GEMV is
// split-K 8 ways with float4 weight loads: per-thread load chains are
// ~10 (projection) and 33 (merge) instead of 74/264, then an 8-way smem
// reduction combines partials. No cp.async, no pipeline, minimal barriers.
// ---------------------------------------------------------------------------
__global__ __launch_bounds__(NTHR2) void stage2(
    const float* __restrict__ stat,
    const float* __restrict__ Ws,  const float* __restrict__ bs,
    const float* __restrict__ Wt,  const float* __restrict__ bt,
    const float* __restrict__ Wst, const float* __restrict__ bst,
    const float* __restrict__ Wm,  const float* __restrict__ bm,
    const float* __restrict__ Wc,  const float* __restrict__ bc,
    float* __restrict__ out) {
    __shared__ float xpart[NF][4];
    __shared__ float xsum[NF];
    __shared__ float part[8][MERGED_];
    __shared__ float comb[MERGED_];
    __shared__ float comb2[MERGED_];
    __shared__ float sden[2];

    const int b = blockIdx.x;
    const int tid = threadIdx.x;

    // ---- Phase A: chunk-partial reduction (4-way split), den/time sums,
    //      static embedding ------------------------------------------------
    if (tid < 4 * NF) {                      // 296 threads
        const int f = tid >> 2, j = tid & 3;
        float a = 0.f;
#pragma unroll
        for (int c = j; c < NCHUNK; c += 4)
            a += g_px[((size_t)c * B_ + b) * NF + f];
        xpart[f][j] = a;
    } else if (tid == 4 * NF) {              // mask-count sum
        float a0 = 0.f, a1 = 0.f, a2 = 0.f, a3 = 0.f;
#pragma unroll
        for (int c = 0; c < NCHUNK; c += 4) {
            a0 += g_pm[c * B_ + b];       a1 += g_pm[(c + 1) * B_ + b];
            a2 += g_pm[(c + 2) * B_ + b]; a3 += g_pm[(c + 3) * B_ + b];
        }
        sden[0] = (a0 + a1) + (a2 + a3);
    } else if (tid == 4 * NF + 1) {          // masked time sum
        float a0 = 0.f, a1 = 0.f, a2 = 0.f, a3 = 0.f;
#pragma unroll
        for (int c = 0; c < NCHUNK; c += 4) {
            a0 += g_pt[c * B_ + b];       a1 += g_pt[(c + 1) * B_ + b];
            a2 += g_pt[(c + 2) * B_ + b]; a3 += g_pt[(c + 3) * B_ + b];
        }
        sden[1] = (a0 + a1) + (a2 + a3);
    } else if (tid >= 448 && tid < 448 + ST_) {
        const int j = tid - 448;
        float p = bst[j];
#pragma unroll
        for (int i = 0; i < ST_; i++) p += stat[b * ST_ + i] * Wst[i * ST_ + j];
        comb[D_ + j] = p;
    }
    __syncthreads();

    // ---- Phase B: combine xsum partials ----------------------------------
    if (tid < NF)
        xsum[tid] = (xpart[tid][0] + xpart[tid][1]) +
                    (xpart[tid][2] + xpart[tid][3]);
    __syncthreads();

    // ---- Phase C: projection partials (split-K 8, float4 over d) ---------
    if (tid < 512) {
        const int d0 = (tid & 63) * 4;
        const int r  = tid >> 6;
        float a0 = 0.f, a1 = 0.f, a2 = 0.f, a3 = 0.f;
        for (int k = r; k < NF; k += 8) {
            const float4 w = *(const float4*)(Ws + (size_t)k * D_ + d0);
            const float c = xsum[k];
            a0 += c * w.x; a1 += c * w.y; a2 += c * w.z; a3 += c * w.w;
        }
        part[r][d0] = a0; part[r][d0 + 1] = a1;
        part[r][d0 + 2] = a2; part[r][d0 + 3] = a3;
    }
    __syncthreads();

    // ---- Phase D: reduce projection, add bias/time terms -----------------
    if (tid < D_) {
        float s = 0.f;
#pragma unroll
        for (int r = 0; r < 8; r++) s += part[r][tid];
        const float den = fmaxf(sden[0], 1e-9f);
        const float tsc = sden[1] / den;
        comb[tid] = s / den + bs[tid] + bt[tid] + tsc * Wt[tid];
    }
    __syncthreads();

    // ---- Phase E: merge partials (split-K 8, float4 over n) --------------
    {
        int n0, r;
        if (tid < 512) { n0 = (tid & 63) * 4; r = tid >> 6; }
        else { const int u = tid - 512; n0 = 256 + (u & 1) * 4; r = u >> 1; }
        float a0 = 0.f, a1 = 0.f, a2 = 0.f, a3 = 0.f;
        for (int k = r; k < MERGED_; k += 8) {
            const float4 w = *(const float4*)(Wm + (size_t)k * MERGED_ + n0);
            const float c = comb[k];
            a0 += c * w.x; a1 += c * w.y; a2 += c * w.z; a3 += c * w.w;
        }
        part[r][n0] = a0; part[r][n0 + 1] = a1;
        part[r][n0 + 2] = a2; part[r][n0 + 3] = a3;
    }
    __syncthreads();

    // ---- Phase F: reduce merge, ReLU -------------------------------------
    if (tid < MERGED_) {
        float s = 0.f;
#pragma unroll
        for (int r = 0; r < 8; r++) s += part[r][tid];
        comb2[tid] = fmaxf(s + bm[tid], 0.f);
    }
    __syncthreads();

    // ---- Phase G: classifier (warps 0,1) ---------------------------------
    const int w = tid >> 5, lane = tid & 31;
    if (w < C_) {
        float p = 0.f;
#pragma unroll
        for (int i = lane; i < MERGED_; i += 32) p += comb2[i] * Wc[i * C_ + w];
        p = wred(p);
        if (lane == 0) out[b * C_ + w] = p + bc[w];
    }
}

extern "C" void kernel_launch(void* const* d_in, const int* in_sizes, int n_in,
                              void* d_out, int out_size) {
    const float* x   = (const float*)d_in[0];
    const float* st  = (const float*)d_in[1];
    const float* tm  = (const float*)d_in[2];
    const int*   smk = (const int*)  d_in[3];
    const float* Ws  = (const float*)d_in[4];
    const float* bs  = (const float*)d_in[5];
    const float* Wt  = (const float*)d_in[6];
    const float* bt  = (const float*)d_in[7];
    const float* Wst = (const float*)d_in[8];
    const float* bst = (const float*)d_in[9];
    const float* Wm  = (const float*)d_in[10];
    const float* bm  = (const float*)d_in[11];
    const float* Wc  = (const float*)d_in[12];
    const float* bc  = (const float*)d_in[13];

    stage1<<<dim3(NCHUNK, B_), 256>>>(x, smk, tm);
    stage2<<<B_, NTHR2>>>(st, Ws, bs, Wt, bt, Wst, bst, Wm, bm, Wc, bc,
                          (float*)d_out);
}

// round 12
// speedup vs baseline: 1.1992x; 1.0010x over previous
#include <cuda_runtime.h>
#include <cstdint>

// Problem shapes
#define B_ 128
#define S_ 37
#define T_ 2048
#define D_ 256
#define ST_ 8
#define C_ 2
#define MERGED_ 264
#define NF (2*S_)          // 74 features (x ++ mask)
#define TC 128             // time chunk per CTA
#define NCHUNK (T_/TC)     // 16
#define NVEC (S_ * TC / 4) // 1184 16B-vectors per tile per tensor

#define NTHR2 528          // stage2 threads

// Per-chunk partial reductions (written without atomics -> deterministic)
__device__ float g_px[(size_t)NCHUNK * B_ * NF];
__device__ float g_pm[NCHUNK * B_];
__device__ float g_pt[NCHUNK * B_];

__device__ __forceinline__ float wred(float v) {
#pragma unroll
    for (int o = 16; o > 0; o >>= 1) v += __shfl_xor_sync(0xffffffffu, v, o);
    return v;
}

// ---------------------------------------------------------------------------
// Stage 1: HBM-roofline pass over x + sensor_mask (77.6 MB).
// Tile load is register-staged: all ~10 LDG.128 issue back-to-back per
// thread (MLP ~10), then the STS batch. No store on the load critical path.
// ---------------------------------------------------------------------------
__global__ __launch_bounds__(256) void stage1(const float* __restrict__ x,
                                              const int*   __restrict__ smk,
                                              const float* __restrict__ tm) {
    __shared__ float xs[S_ * TC];
    __shared__ int   msi[S_ * TC];
    __shared__ float valid[TC];
    __shared__ float red[8][2];

    const int chunk = blockIdx.x;
    const int b     = blockIdx.y;
    const int t0    = chunk * TC;
    const int tid   = threadIdx.x;

    const float* xb = x   + (size_t)b * S_ * T_ + t0;
    const int*   mb = smk + (size_t)b * S_ * T_ + t0;

    // ---- register-staged tile load (batched LDG, then batched STS) -------
    {
        float4 rx[5];
        int4   rm[5];
#pragma unroll
        for (int i = 0; i < 5; i++) {
            const int idx = tid + 256 * i;
            if (idx < NVEC) {
                const int s = idx >> 5;           // idx / (TC/4)
                const int j = (idx & 31) * 4;     // 0..124
                rx[i] = *(const float4*)(xb + (size_t)s * T_ + j);
                rm[i] = *(const int4*)  (mb + (size_t)s * T_ + j);
            }
        }
#pragma unroll
        for (int i = 0; i < 5; i++) {
            const int idx = tid + 256 * i;
            if (idx < NVEC) {
                const int s = idx >> 5;
                const int j = (idx & 31) * 4;
                *(float4*)(xs + s * TC + j) = rx[i];
                *(int4*)(msi + s * TC + j)  = rm[i];
            }
        }
    }
    __syncthreads();

    float vf = 0.f, tv = 0.f;
    if (tid < TC) {
        const int t = tid;
        int nz = 0;
#pragma unroll
        for (int s = 0; s < S_; s++) {
            nz |= (xs[s * TC + t] != 0.f);
            nz |= (msi[s * TC + t] != 0);
        }
        vf = nz ? 1.f : 0.f;
        valid[t] = vf;
        tv = vf * tm[(size_t)b * T_ + t0 + t];
    }

    const int w = tid >> 5, lane = tid & 31;
    float rv = wred(vf), rt = wred(tv);
    if (lane == 0) { red[w][0] = rv; red[w][1] = rt; }
    __syncthreads();
    if (tid == 0) {
        float a = 0.f, c = 0.f;
#pragma unroll
        for (int i = 0; i < 8; i++) { a += red[i][0]; c += red[i][1]; }
        g_pm[chunk * B_ + b] = a;
        g_pt[chunk * B_ + b] = c;
    }

    for (int f = w; f < NF; f += 8) {
        float p = 0.f;
        if (f < S_) {
            const float* src = xs + f * TC;
#pragma unroll
            for (int j = lane; j < TC; j += 32) p += valid[j] * src[j];
        } else {
            const int* src = msi + (f - S_) * TC;
#pragma unroll
            for (int j = lane; j < TC; j += 32) p += valid[j] * (float)src[j];
        }
        p = wred(p);
        if (lane == 0) g_px[((size_t)chunk * B_ + b) * NF + f] = p;
    }
}

// ---------------------------------------------------------------------------
// Stage 2: one CTA per batch (128 CTAs x 528 threads). Every GEMV is
// split-K 8 ways with float4 weight loads; 8-way smem reduction combines.
// ---------------------------------------------------------------------------
__global__ __launch_bounds__(NTHR2) void stage2(
    const float* __restrict__ stat,
    const float* __restrict__ Ws,  const float* __restrict__ bs,
    const float* __restrict__ Wt,  const float* __restrict__ bt,
    const float* __restrict__ Wst, const float* __restrict__ bst,
    const float* __restrict__ Wm,  const float* __restrict__ bm,
    const float* __restrict__ Wc,  const float* __restrict__ bc,
    float* __restrict__ out) {
    __shared__ float xpart[NF][4];
    __shared__ float xsum[NF];
    __shared__ float part[8][MERGED_];
    __shared__ float comb[MERGED_];
    __shared__ float comb2[MERGED_];
    __shared__ float sden[2];

    const int b = blockIdx.x;
    const int tid = threadIdx.x;

    // ---- Phase A: chunk-partial reduction (4-way split), den/time sums,
    //      static embedding ------------------------------------------------
    if (tid < 4 * NF) {                      // 296 threads
        const int f = tid >> 2, j = tid & 3;
        float a = 0.f;
#pragma unroll
        for (int c = j; c < NCHUNK; c += 4)
            a += g_px[((size_t)c * B_ + b) * NF + f];
        xpart[f][j] = a;
    } else if (tid == 4 * NF) {              // mask-count sum
        float a0 = 0.f, a1 = 0.f, a2 = 0.f, a3 = 0.f;
#pragma unroll
        for (int c = 0; c < NCHUNK; c += 4) {
            a0 += g_pm[c * B_ + b];       a1 += g_pm[(c + 1) * B_ + b];
            a2 += g_pm[(c + 2) * B_ + b]; a3 += g_pm[(c + 3) * B_ + b];
        }
        sden[0] = (a0 + a1) + (a2 + a3);
    } else if (tid == 4 * NF + 1) {          // masked time sum
        float a0 = 0.f, a1 = 0.f, a2 = 0.f, a3 = 0.f;
#pragma unroll
        for (int c = 0; c < NCHUNK; c += 4) {
            a0 += g_pt[c * B_ + b];       a1 += g_pt[(c + 1) * B_ + b];
            a2 += g_pt[(c + 2) * B_ + b]; a3 += g_pt[(c + 3) * B_ + b];
        }
        sden[1] = (a0 + a1) + (a2 + a3);
    } else if (tid >= 448 && tid < 448 + ST_) {
        const int j = tid - 448;
        float p = bst[j];
#pragma unroll
        for (int i = 0; i < ST_; i++) p += stat[b * ST_ + i] * Wst[i * ST_ + j];
        comb[D_ + j] = p;
    }
    __syncthreads();

    // ---- Phase B: combine xsum partials ----------------------------------
    if (tid < NF)
        xsum[tid] = (xpart[tid][0] + xpart[tid][1]) +
                    (xpart[tid][2] + xpart[tid][3]);
    __syncthreads();

    // ---- Phase C: projection partials (split-K 8, float4 over d) ---------
    if (tid < 512) {
        const int d0 = (tid & 63) * 4;
        const int r  = tid >> 6;
        float a0 = 0.f, a1 = 0.f, a2 = 0.f, a3 = 0.f;
        for (int k = r; k < NF; k += 8) {
            const float4 w = *(const float4*)(Ws + (size_t)k * D_ + d0);
            const float c = xsum[k];
            a0 += c * w.x; a1 += c * w.y; a2 += c * w.z; a3 += c * w.w;
        }
        part[r][d0] = a0; part[r][d0 + 1] = a1;
        part[r][d0 + 2] = a2; part[r][d0 + 3] = a3;
    }
    __syncthreads();

    // ---- Phase D: reduce projection, add bias/time terms -----------------
    if (tid < D_) {
        float s = 0.f;
#pragma unroll
        for (int r = 0; r < 8; r++) s += part[r][tid];
        const float den = fmaxf(sden[0], 1e-9f);
        const float tsc = sden[1] / den;
        comb[tid] = s / den + bs[tid] + bt[tid] + tsc * Wt[tid];
    }
    __syncthreads();

    // ---- Phase E: merge partials (split-K 8, float4 over n) --------------
    {
        int n0, r;
        if (tid < 512) { n0 = (tid & 63) * 4; r = tid >> 6; }
        else { const int u = tid - 512; n0 = 256 + (u & 1) * 4; r = u >> 1; }
        float a0 = 0.f, a1 = 0.f, a2 = 0.f, a3 = 0.f;
        for (int k = r; k < MERGED_; k += 8) {
            const float4 w = *(const float4*)(Wm + (size_t)k * MERGED_ + n0);
            const float c = comb[k];
            a0 += c * w.x; a1 += c * w.y; a2 += c * w.z; a3 += c * w.w;
        }
        part[r][n0] = a0; part[r][n0 + 1] = a1;
        part[r][n0 + 2] = a2; part[r][n0 + 3] = a3;
    }
    __syncthreads();

    // ---- Phase F: reduce merge, ReLU -------------------------------------
    if (tid < MERGED_) {
        float s = 0.f;
#pragma unroll
        for (int r = 0; r < 8; r++) s += part[r][tid];
        comb2[tid] = fmaxf(s + bm[tid], 0.f);
    }
    __syncthreads();

    // ---- Phase G: classifier (warps 0,1) ---------------------------------
    const int w = tid >> 5, lane = tid & 31;
    if (w < C_) {
        float p = 0.f;
#pragma unroll
        for (int i = lane; i < MERGED_; i += 32) p += comb2[i] * Wc[i * C_ + w];
        p = wred(p);
        if (lane == 0) out[b * C_ + w] = p + bc[w];
    }
}

extern "C" void kernel_launch(void* const* d_in, const int* in_sizes, int n_in,
                              void* d_out, int out_size) {
    const float* x   = (const float*)d_in[0];
    const float* st  = (const float*)d_in[1];
    const float* tm  = (const float*)d_in[2];
    const int*   smk = (const int*)  d_in[3];
    const float* Ws  = (const float*)d_in[4];
    const float* bs  = (const float*)d_in[5];
    const float* Wt  = (const float*)d_in[6];
    const float* bt  = (const float*)d_in[7];
    const float* Wst = (const float*)d_in[8];
    const float* bst = (const float*)d_in[9];
    const float* Wm  = (const float*)d_in[10];
    const float* bm  = (const float*)d_in[11];
    const float* Wc  = (const float*)d_in[12];
    const float* bc  = (const float*)d_in[13];

    stage1<<<dim3(NCHUNK, B_), 256>>>(x, smk, tm);
    stage2<<<B_, NTHR2>>>(st, Ws, bs, Wt, bt, Wst, bst, Wm, bm, Wc, bc,
                          (float*)d_out);
}

// round 13
// speedup vs baseline: 1.2709x; 1.0598x over previous
#include <cuda_runtime.h>
#include <cstdint>

// Problem shapes
#define B_ 128
#define S_ 37
#define T_ 2048
#define D_ 256
#define ST_ 8
#define C_ 2
#define MERGED_ 264
#define NF (2*S_)          // 74 features (x ++ mask)
#define TC 128             // time chunk per CTA
#define NCHUNK (T_/TC)     // 16
#define NVEC (S_ * TC / 4) // 1184 16B-vectors per tile per tensor

#define NTHR2 528          // stage2 threads = 66 quads * 8 ranks

// Per-chunk partial reductions (written without atomics -> deterministic)
__device__ float g_px[(size_t)NCHUNK * B_ * NF];
__device__ float g_pm[NCHUNK * B_];
__device__ float g_pt[NCHUNK * B_];

__device__ __forceinline__ float wred(float v) {
#pragma unroll
    for (int o = 16; o > 0; o >>= 1) v += __shfl_xor_sync(0xffffffffu, v, o);
    return v;
}

// ---------------------------------------------------------------------------
// Stage 1: HBM-roofline pass over x + sensor_mask (77.6 MB).
// Register-staged tile load: all ~10 LDG.128 in flight, then the STS batch.
// ---------------------------------------------------------------------------
__global__ __launch_bounds__(256) void stage1(const float* __restrict__ x,
                                              const int*   __restrict__ smk,
                                              const float* __restrict__ tm) {
    __shared__ float xs[S_ * TC];
    __shared__ int   msi[S_ * TC];
    __shared__ float valid[TC];
    __shared__ float red[8][2];

    const int chunk = blockIdx.x;
    const int b     = blockIdx.y;
    const int t0    = chunk * TC;
    const int tid   = threadIdx.x;

    const float* xb = x   + (size_t)b * S_ * T_ + t0;
    const int*   mb = smk + (size_t)b * S_ * T_ + t0;

    {
        float4 rx[5];
        int4   rm[5];
#pragma unroll
        for (int i = 0; i < 5; i++) {
            const int idx = tid + 256 * i;
            if (idx < NVEC) {
                const int s = idx >> 5;
                const int j = (idx & 31) * 4;
                rx[i] = *(const float4*)(xb + (size_t)s * T_ + j);
                rm[i] = *(const int4*)  (mb + (size_t)s * T_ + j);
            }
        }
#pragma unroll
        for (int i = 0; i < 5; i++) {
            const int idx = tid + 256 * i;
            if (idx < NVEC) {
                const int s = idx >> 5;
                const int j = (idx & 31) * 4;
                *(float4*)(xs + s * TC + j) = rx[i];
                *(int4*)(msi + s * TC + j)  = rm[i];
            }
        }
    }
    __syncthreads();

    float vf = 0.f, tv = 0.f;
    if (tid < TC) {
        const int t = tid;
        int nz = 0;
#pragma unroll
        for (int s = 0; s < S_; s++) {
            nz |= (xs[s * TC + t] != 0.f);
            nz |= (msi[s * TC + t] != 0);
        }
        vf = nz ? 1.f : 0.f;
        valid[t] = vf;
        tv = vf * tm[(size_t)b * T_ + t0 + t];
    }

    const int w = tid >> 5, lane = tid & 31;
    float rv = wred(vf), rt = wred(tv);
    if (lane == 0) { red[w][0] = rv; red[w][1] = rt; }
    __syncthreads();
    if (tid == 0) {
        float a = 0.f, c = 0.f;
#pragma unroll
        for (int i = 0; i < 8; i++) { a += red[i][0]; c += red[i][1]; }
        g_pm[chunk * B_ + b] = a;
        g_pt[chunk * B_ + b] = c;
    }

    for (int f = w; f < NF; f += 8) {
        float p = 0.f;
        if (f < S_) {
            const float* src = xs + f * TC;
#pragma unroll
            for (int j = lane; j < TC; j += 32) p += valid[j] * src[j];
        } else {
            const int* src = msi + (f - S_) * TC;
#pragma unroll
            for (int j = lane; j < TC; j += 32) p += valid[j] * (float)src[j];
        }
        p = wred(p);
        if (lane == 0) g_px[((size_t)chunk * B_ + b) * NF + f] = p;
    }
}

// ---------------------------------------------------------------------------
// Stage 2: one CTA per batch (128 x 528). Split-K GEMVs with COMPILE-TIME
// trip counts (k = r + 8*i, literal i-bounds) + unroll 8 so ptxas keeps
// ~8 independent LDG.128 in flight per thread.
// ---------------------------------------------------------------------------
__global__ __launch_bounds__(NTHR2, 1) void stage2(
    const float* __restrict__ stat,
    const float* __restrict__ Ws,  const float* __restrict__ bs,
    const float* __restrict__ Wt,  const float* __restrict__ bt,
    const float* __restrict__ Wst, const float* __restrict__ bst,
    const float* __restrict__ Wm,  const float* __restrict__ bm,
    const float* __restrict__ Wc,  const float* __restrict__ bc,
    float* __restrict__ out) {
    __shared__ float xpart[NF][4];
    __shared__ float xsum[NF];
    __shared__ float part[8][MERGED_];
    __shared__ float comb[MERGED_];
    __shared__ float comb2[MERGED_];
    __shared__ float sden[2];

    const int b = blockIdx.x;
    const int tid = threadIdx.x;

    // ---- Phase A: chunk-partial reduction (4-way), den/time, static ------
    if (tid < 4 * NF) {
        const int f = tid >> 2, j = tid & 3;
        float a0 = 0.f, a1 = 0.f, a2 = 0.f, a3 = 0.f;
        const float* base = g_px + (size_t)j * B_ * NF + (size_t)b * NF + f;
        a0 = base[0];
        a1 = base[(size_t)4 * B_ * NF];
        a2 = base[(size_t)8 * B_ * NF];
        a3 = base[(size_t)12 * B_ * NF];
        xpart[f][j] = (a0 + a1) + (a2 + a3);
    } else if (tid == 4 * NF) {
        float a0 = 0.f, a1 = 0.f, a2 = 0.f, a3 = 0.f;
#pragma unroll
        for (int c = 0; c < NCHUNK; c += 4) {
            a0 += g_pm[c * B_ + b];       a1 += g_pm[(c + 1) * B_ + b];
            a2 += g_pm[(c + 2) * B_ + b]; a3 += g_pm[(c + 3) * B_ + b];
        }
        sden[0] = (a0 + a1) + (a2 + a3);
    } else if (tid == 4 * NF + 1) {
        float a0 = 0.f, a1 = 0.f, a2 = 0.f, a3 = 0.f;
#pragma unroll
        for (int c = 0; c < NCHUNK; c += 4) {
            a0 += g_pt[c * B_ + b];       a1 += g_pt[(c + 1) * B_ + b];
            a2 += g_pt[(c + 2) * B_ + b]; a3 += g_pt[(c + 3) * B_ + b];
        }
        sden[1] = (a0 + a1) + (a2 + a3);
    } else if (tid >= 448 && tid < 448 + ST_) {
        const int j = tid - 448;
        float p = bst[j];
#pragma unroll
        for (int i = 0; i < ST_; i++) p += stat[b * ST_ + i] * Wst[i * ST_ + j];
        comb[D_ + j] = p;
    }
    __syncthreads();

    // ---- Phase B: combine xsum partials ----------------------------------
    if (tid < NF)
        xsum[tid] = (xpart[tid][0] + xpart[tid][1]) +
                    (xpart[tid][2] + xpart[tid][3]);
    __syncthreads();

    // ---- Phase C: projection partials (512 thr = 64 quads x 8 ranks) -----
    if (tid < 512) {
        const int d0 = (tid & 63) * 4;
        const int r  = tid >> 6;
        float a0 = 0.f, a1 = 0.f, a2 = 0.f, a3 = 0.f;
#pragma unroll
        for (int i = 0; i < 9; i++) {          // k = r + 8i <= 71, literal
            const int k = r + 8 * i;
            const float4 w = *(const float4*)(Ws + (size_t)k * D_ + d0);
            const float c = xsum[k];
            a0 += c * w.x; a1 += c * w.y; a2 += c * w.z; a3 += c * w.w;
        }
        if (r < 2) {                           // tail k = 72, 73
            const int k = 72 + r;
            const float4 w = *(const float4*)(Ws + (size_t)k * D_ + d0);
            const float c = xsum[k];
            a0 += c * w.x; a1 += c * w.y; a2 += c * w.z; a3 += c * w.w;
        }
        part[r][d0] = a0; part[r][d0 + 1] = a1;
        part[r][d0 + 2] = a2; part[r][d0 + 3] = a3;
    }
    __syncthreads();

    // ---- Phase D: reduce projection, add bias/time terms -----------------
    if (tid < D_) {
        float s = 0.f;
#pragma unroll
        for (int r = 0; r < 8; r++) s += part[r][tid];
        const float den = fmaxf(sden[0], 1e-9f);
        const float tsc = sden[1] / den;
        comb[tid] = s / den + bs[tid] + bt[tid] + tsc * Wt[tid];
    }
    __syncthreads();

    // ---- Phase E: merge partials (528 thr = 66 quads x 8 ranks) ----------
    {
        const int q = tid % 66, r = tid / 66;
        const int n0 = q * 4;
        float a0 = 0.f, a1 = 0.f, a2 = 0.f, a3 = 0.f;
#pragma unroll 8
        for (int i = 0; i < 33; i++) {         // k = r + 8i <= 263, literal
            const int k = r + 8 * i;
            const float4 w = *(const float4*)(Wm + (size_t)k * MERGED_ + n0);
            const float c = comb[k];
            a0 += c * w.x; a1 += c * w.y; a2 += c * w.z; a3 += c * w.w;
        }
        part[r][n0] = a0; part[r][n0 + 1] = a1;
        part[r][n0 + 2] = a2; part[r][n0 + 3] = a3;
    }
    __syncthreads();

    // ---- Phase F: reduce merge, ReLU -------------------------------------
    if (tid < MERGED_) {
        float s = 0.f;
#pragma unroll
        for (int r = 0; r < 8; r++) s += part[r][tid];
        comb2[tid] = fmaxf(s + bm[tid], 0.f);
    }
    __syncthreads();

    // ---- Phase G: classifier (warps 0,1) ---------------------------------
    const int w = tid >> 5, lane = tid & 31;
    if (w < C_) {
        float p = 0.f;
#pragma unroll
        for (int i = lane; i < MERGED_; i += 32) p += comb2[i] * Wc[i * C_ + w];
        p = wred(p);
        if (lane == 0) out[b * C_ + w] = p + bc[w];
    }
}

extern "C" void kernel_launch(void* const* d_in, const int* in_sizes, int n_in,
                              void* d_out, int out_size) {
    const float* x   = (const float*)d_in[0];
    const float* st  = (const float*)d_in[1];
    const float* tm  = (const float*)d_in[2];
    const int*   smk = (const int*)  d_in[3];
    const float* Ws  = (const float*)d_in[4];
    const float* bs  = (const float*)d_in[5];
    const float* Wt  = (const float*)d_in[6];
    const float* bt  = (const float*)d_in[7];
    const float* Wst = (const float*)d_in[8];
    const float* bst = (const float*)d_in[9];
    const float* Wm  = (const float*)d_in[10];
    const float* bm  = (const float*)d_in[11];
    const float* Wc  = (const float*)d_in[12];
    const float* bc  = (const float*)d_in[13];

    stage1<<<dim3(NCHUNK, B_), 256>>>(x, smk, tm);
    stage2<<<B_, NTHR2>>>(st, Ws, bs, Wt, bt, Wst, bst, Wm, bm, Wc, bc,
                          (float*)d_out);
}

// round 14
// speedup vs baseline: 1.7997x; 1.4160x over previous
#include <cuda_runtime.h>
#include <cstdint>

// Problem shapes
#define B_ 128
#define S_ 37
#define T_ 2048
#define D_ 256
#define ST_ 8
#define C_ 2
#define MERGED_ 264
#define NF (2*S_)          // 74 features (x ++ mask)
#define TC 128             // time chunk
#define NGRP 4             // chunk groups (CTAs per batch in stage1)
#define CPG 4              // chunks per group (NGRP*CPG*TC = T)

#define NTHR2 528          // stage2 threads = 66 quads * 8 ranks

// Per-group partial reductions (written without atomics -> deterministic)
__device__ float g_px[(size_t)NGRP * B_ * NF];
__device__ float g_pm[NGRP * B_];
__device__ float g_pt[NGRP * B_];

__device__ __forceinline__ float wred(float v) {
#pragma unroll
    for (int o = 16; o > 0; o >>= 1) v += __shfl_xor_sync(0xffffffffu, v, o);
    return v;
}

// ---------------------------------------------------------------------------
// Stage 1: register-resident pass over x + sensor_mask (77.6 MB).
// Warp w, batch i owns row s=w+8i; lane l holds t=4l..4l+3 in registers.
// Only tiny nz-words + valid flags touch smem (no tile staging). Feature
// sums accumulate lane-locally across 4 chunks; one wred per row at the end.
// ---------------------------------------------------------------------------
__global__ __launch_bounds__(256) void stage1(const float* __restrict__ x,
                                              const int*   __restrict__ smk,
                                              const float* __restrict__ tm) {
    __shared__ unsigned nzw[S_][32];
    __shared__ __align__(16) float validf[TC];

    const int g   = blockIdx.x;          // chunk group 0..3
    const int b   = blockIdx.y;
    const int tid = threadIdx.x;
    const int w = tid >> 5, lane = tid & 31;
    const int nb = (w < 5) ? 5 : 4;      // rows handled by this warp

    const float* xb0 = x   + (size_t)b * S_ * T_;
    const int*   mb0 = smk + (size_t)b * S_ * T_;

    float accx[5], accm[5];
#pragma unroll
    for (int i = 0; i < 5; i++) { accx[i] = 0.f; accm[i] = 0.f; }
    float cnt = 0.f, tsum = 0.f;         // warp 0 lane-partials

    float4 rx[5];
    int4   rm[5];
    // preload chunk 0 of this group
    {
        const int t0 = g * CPG * TC;
#pragma unroll
        for (int i = 0; i < 5; i++) if (i < nb) {
            const int s = w + 8 * i;
            rx[i] = *(const float4*)(xb0 + (size_t)s * T_ + t0 + 4 * lane);
            rm[i] = *(const int4*)  (mb0 + (size_t)s * T_ + t0 + 4 * lane);
        }
    }

#pragma unroll
    for (int c = 0; c < CPG; c++) {
        const int t0 = (g * CPG + c) * TC;

        // nz word per register vector (4 bool bytes)
#pragma unroll
        for (int i = 0; i < 5; i++) if (i < nb) {
            unsigned nz = 0;
            nz |= ((rx[i].x != 0.f) || (rm[i].x != 0)) ? 0x01u : 0u;
            nz |= ((rx[i].y != 0.f) || (rm[i].y != 0)) ? 0x0100u : 0u;
            nz |= ((rx[i].z != 0.f) || (rm[i].z != 0)) ? 0x010000u : 0u;
            nz |= ((rx[i].w != 0.f) || (rm[i].w != 0)) ? 0x01000000u : 0u;
            nzw[w + 8 * i][lane] = nz;
        }
        __syncthreads();

        if (w == 0) {
            unsigned o = 0;
#pragma unroll
            for (int s = 0; s < S_; s++) o |= nzw[s][lane];
            const float v0 = (o & 0x000000FFu) ? 1.f : 0.f;
            const float v1 = (o & 0x0000FF00u) ? 1.f : 0.f;
            const float v2 = (o & 0x00FF0000u) ? 1.f : 0.f;
            const float v3 = (o & 0xFF000000u) ? 1.f : 0.f;
            *(float4*)&validf[4 * lane] = make_float4(v0, v1, v2, v3);
            const float4 tq = *(const float4*)(tm + (size_t)b * T_ + t0 + 4 * lane);
            cnt  += (v0 + v1) + (v2 + v3);
            tsum += v0 * tq.x + v1 * tq.y + v2 * tq.z + v3 * tq.w;
        }
        __syncthreads();

        // feature dots from registers, lane-local accumulation
        const float4 v = *(const float4*)&validf[4 * lane];
#pragma unroll
        for (int i = 0; i < 5; i++) if (i < nb) {
            accx[i] += v.x * rx[i].x + v.y * rx[i].y +
                       v.z * rx[i].z + v.w * rx[i].w;
            accm[i] += v.x * (float)rm[i].x + v.y * (float)rm[i].y +
                       v.z * (float)rm[i].z + v.w * (float)rm[i].w;
        }

        // issue next chunk's loads (hidden behind next nz/valid phases)
        if (c < CPG - 1) {
            const int t1 = t0 + TC;
#pragma unroll
            for (int i = 0; i < 5; i++) if (i < nb) {
                const int s = w + 8 * i;
                rx[i] = *(const float4*)(xb0 + (size_t)s * T_ + t1 + 4 * lane);
                rm[i] = *(const int4*)  (mb0 + (size_t)s * T_ + t1 + 4 * lane);
            }
        }
    }

    // final reductions + writes
#pragma unroll
    for (int i = 0; i < 5; i++) if (i < nb) {
        const float sx = wred(accx[i]);
        const float sm = wred(accm[i]);
        if (lane == 0) {
            const int s = w + 8 * i;
            float* dst = g_px + ((size_t)g * B_ + b) * NF;
            dst[s]      = sx;
            dst[S_ + s] = sm;
        }
    }
    if (w == 0) {
        const float rc = wred(cnt);
        const float rt = wred(tsum);
        if (lane == 0) { g_pm[g * B_ + b] = rc; g_pt[g * B_ + b] = rt; }
    }
}

// ---------------------------------------------------------------------------
// Stage 2: one CTA per batch (128 x 528). Split-K GEMVs with compile-time
// trip counts + unroll so ~8 independent LDG.128 stay in flight per thread.
// ---------------------------------------------------------------------------
__global__ __launch_bounds__(NTHR2, 1) void stage2(
    const float* __restrict__ stat,
    const float* __restrict__ Ws,  const float* __restrict__ bs,
    const float* __restrict__ Wt,  const float* __restrict__ bt,
    const float* __restrict__ Wst, const float* __restrict__ bst,
    const float* __restrict__ Wm,  const float* __restrict__ bm,
    const float* __restrict__ Wc,  const float* __restrict__ bc,
    float* __restrict__ out) {
    __shared__ float xpart[NF][4];
    __shared__ float xsum[NF];
    __shared__ float part[8][MERGED_];
    __shared__ float comb[MERGED_];
    __shared__ float comb2[MERGED_];
    __shared__ float sden[2];

    const int b = blockIdx.x;
    const int tid = threadIdx.x;

    // ---- Phase A: group-partial gather (1 load/thread), den/time, static -
    if (tid < 4 * NF) {
        const int f = tid >> 2, j = tid & 3;
        xpart[f][j] = g_px[((size_t)j * B_ + b) * NF + f];
    } else if (tid == 4 * NF) {
        sden[0] = (g_pm[0 * B_ + b] + g_pm[1 * B_ + b]) +
                  (g_pm[2 * B_ + b] + g_pm[3 * B_ + b]);
    } else if (tid == 4 * NF + 1) {
        sden[1] = (g_pt[0 * B_ + b] + g_pt[1 * B_ + b]) +
                  (g_pt[2 * B_ + b] + g_pt[3 * B_ + b]);
    } else if (tid >= 448 && tid < 448 + ST_) {
        const int j = tid - 448;
        float p = bst[j];
#pragma unroll
        for (int i = 0; i < ST_; i++) p += stat[b * ST_ + i] * Wst[i * ST_ + j];
        comb[D_ + j] = p;
    }
    __syncthreads();

    // ---- Phase B: combine xsum partials ----------------------------------
    if (tid < NF)
        xsum[tid] = (xpart[tid][0] + xpart[tid][1]) +
                    (xpart[tid][2] + xpart[tid][3]);
    __syncthreads();

    // ---- Phase C: projection partials (512 thr = 64 quads x 8 ranks) -----
    if (tid < 512) {
        const int d0 = (tid & 63) * 4;
        const int r  = tid >> 6;
        float a0 = 0.f, a1 = 0.f, a2 = 0.f, a3 = 0.f;
#pragma unroll
        for (int i = 0; i < 9; i++) {          // k = r + 8i <= 71, literal
            const int k = r + 8 * i;
            const float4 w = *(const float4*)(Ws + (size_t)k * D_ + d0);
            const float c = xsum[k];
            a0 += c * w.x; a1 += c * w.y; a2 += c * w.z; a3 += c * w.w;
        }
        if (r < 2) {                           // tail k = 72, 73
            const int k = 72 + r;
            const float4 w = *(const float4*)(Ws + (size_t)k * D_ + d0);
            const float c = xsum[k];
            a0 += c * w.x; a1 += c * w.y; a2 += c * w.z; a3 += c * w.w;
        }
        part[r][d0] = a0; part[r][d0 + 1] = a1;
        part[r][d0 + 2] = a2; part[r][d0 + 3] = a3;
    }
    __syncthreads();

    // ---- Phase D: reduce projection, add bias/time terms -----------------
    if (tid < D_) {
        float s = 0.f;
#pragma unroll
        for (int r = 0; r < 8; r++) s += part[r][tid];
        const float den = fmaxf(sden[0], 1e-9f);
        const float tsc = sden[1] / den;
        comb[tid] = s / den + bs[tid] + bt[tid] + tsc * Wt[tid];
    }
    __syncthreads();

    // ---- Phase E: merge partials (528 thr = 66 quads x 8 ranks) ----------
    {
        const int q = tid % 66, r = tid / 66;
        const int n0 = q * 4;
        float a0 = 0.f, a1 = 0.f, a2 = 0.f, a3 = 0.f;
#pragma unroll 8
        for (int i = 0; i < 33; i++) {         // k = r + 8i <= 263, literal
            const int k = r + 8 * i;
            const float4 w = *(const float4*)(Wm + (size_t)k * MERGED_ + n0);
            const float c = comb[k];
            a0 += c * w.x; a1 += c * w.y; a2 += c * w.z; a3 += c * w.w;
        }
        part[r][n0] = a0; part[r][n0 + 1] = a1;
        part[r][n0 + 2] = a2; part[r][n0 + 3] = a3;
    }
    __syncthreads();

    // ---- Phase F: reduce merge, ReLU -------------------------------------
    if (tid < MERGED_) {
        float s = 0.f;
#pragma unroll
        for (int r = 0; r < 8; r++) s += part[r][tid];
        comb2[tid] = fmaxf(s + bm[tid], 0.f);
    }
    __syncthreads();

    // ---- Phase G: classifier (warps 0,1) ---------------------------------
    const int w = tid >> 5, lane = tid & 31;
    if (w < C_) {
        float p = 0.f;
#pragma unroll
        for (int i = lane; i < MERGED_; i += 32) p += comb2[i] * Wc[i * C_ + w];
        p = wred(p);
        if (lane == 0) out[b * C_ + w] = p + bc[w];
    }
}

extern "C" void kernel_launch(void* const* d_in, const int* in_sizes, int n_in,
                              void* d_out, int out_size) {
    const float* x   = (const float*)d_in[0];
    const float* st  = (const float*)d_in[1];
    const float* tm  = (const float*)d_in[2];
    const int*   smk = (const int*)  d_in[3];
    const float* Ws  = (const float*)d_in[4];
    const float* bs  = (const float*)d_in[5];
    const float* Wt  = (const float*)d_in[6];
    const float* bt  = (const float*)d_in[7];
    const float* Wst = (const float*)d_in[8];
    const float* bst = (const float*)d_in[9];
    const float* Wm  = (const float*)d_in[10];
    const float* bm  = (const float*)d_in[11];
    const float* Wc  = (const float*)d_in[12];
    const float* bc  = (const float*)d_in[13];

    stage1<<<dim3(NGRP, B_), 256>>>(x, smk, tm);
    stage2<<<B_, NTHR2>>>(st, Ws, bs, Wt, bt, Wst, bst, Wm, bm, Wc, bc,
                          (float*)d_out);
}

// round 17
// speedup vs baseline: 1.8658x; 1.0367x over previous
#include <cuda_runtime.h>
#include <cstdint>

// Problem shapes
#define B_ 128
#define S_ 37
#define T_ 2048
#define D_ 256
#define ST_ 8
#define C_ 2
#define MERGED_ 264
#define NF (2*S_)          // 74 features (x ++ mask)
#define TC 128             // time chunk
#define NGRP 2             // chunk groups (CTAs per batch in stage1)
#define CPG 8              // chunks per group (NGRP*CPG*TC = T)

#define NTHR2 528          // stage2 threads = 66 quads * 8 ranks

// Per-group partial reductions (written without atomics -> deterministic)
__device__ float g_px[(size_t)NGRP * B_ * NF];
__device__ float g_pm[NGRP * B_];
__device__ float g_pt[NGRP * B_];

__device__ __forceinline__ float wred(float v) {
#pragma unroll
    for (int o = 16; o > 0; o >>= 1) v += __shfl_xor_sync(0xffffffffu, v, o);
    return v;
}

// ---------------------------------------------------------------------------
// Stage 1: register-resident, software-pipelined pass over x + sensor_mask.
// Double-buffered: chunk c+1's LDGs are in flight while chunk c's nz/valid/
// dot phases (and their two barriers) execute. Only tiny nz words + valid
// flags touch shared memory.
// ---------------------------------------------------------------------------
#define LOADC(RX, RM, TQ, T0)                                                 \
    {                                                                         \
        _Pragma("unroll")                                                     \
        for (int i = 0; i < 5; i++) if (i < nb) {                             \
            const int s = w + 8 * i;                                          \
            RX[i] = *(const float4*)(xb0 + (size_t)s * T_ + (T0) + 4 * lane); \
            RM[i] = *(const int4*)  (mb0 + (size_t)s * T_ + (T0) + 4 * lane); \
        }                                                                     \
        if (w == 0) TQ = *(const float4*)(tb + (T0) + 4 * lane);              \
    }

#define PROCC(RX, RM, TQ)                                                     \
    {                                                                         \
        _Pragma("unroll")                                                     \
        for (int i = 0; i < 5; i++) if (i < nb) {                             \
            unsigned nz = 0;                                                  \
            nz |= ((RX[i].x != 0.f) || (RM[i].x != 0)) ? 0x01u : 0u;          \
            nz |= ((RX[i].y != 0.f) || (RM[i].y != 0)) ? 0x0100u : 0u;        \
            nz |= ((RX[i].z != 0.f) || (RM[i].z != 0)) ? 0x010000u : 0u;      \
            nz |= ((RX[i].w != 0.f) || (RM[i].w != 0)) ? 0x01000000u : 0u;    \
            nzw[w + 8 * i][lane] = nz;                                        \
        }                                                                     \
        __syncthreads();                                                      \
        if (w == 0) {                                                         \
            unsigned o = 0;                                                   \
            _Pragma("unroll")                                                 \
            for (int s = 0; s < S_; s++) o |= nzw[s][lane];                   \
            const float v0 = (o & 0x000000FFu) ? 1.f : 0.f;                   \
            const float v1 = (o & 0x0000FF00u) ? 1.f : 0.f;                   \
            const float v2 = (o & 0x00FF0000u) ? 1.f : 0.f;                   \
            const float v3 = (o & 0xFF000000u) ? 1.f : 0.f;                   \
            *(float4*)&validf[4 * lane] = make_float4(v0, v1, v2, v3);        \
            cnt  += (v0 + v1) + (v2 + v3);                                    \
            tsum += v0 * TQ.x + v1 * TQ.y + v2 * TQ.z + v3 * TQ.w;            \
        }                                                                     \
        __syncthreads();                                                      \
        const float4 v = *(const float4*)&validf[4 * lane];                   \
        _Pragma("unroll")                                                     \
        for (int i = 0; i < 5; i++) if (i < nb) {                             \
            accx[i] += v.x * RX[i].x + v.y * RX[i].y +                        \
                       v.z * RX[i].z + v.w * RX[i].w;                         \
            accm[i] += v.x * (float)RM[i].x + v.y * (float)RM[i].y +          \
                       v.z * (float)RM[i].z + v.w * (float)RM[i].w;           \
        }                                                                     \
    }

__global__ __launch_bounds__(256, 2) void stage1(const float* __restrict__ x,
                                                 const int*   __restrict__ smk,
                                                 const float* __restrict__ tm) {
    __shared__ unsigned nzw[S_][32];
    __shared__ __align__(16) float validf[TC];

    const int g   = blockIdx.x;          // chunk group 0..NGRP-1
    const int b   = blockIdx.y;
    const int tid = threadIdx.x;
    const int w = tid >> 5, lane = tid & 31;
    const int nb = (w < 5) ? 5 : 4;      // rows handled by this warp

    const float* xb0 = x   + (size_t)b * S_ * T_;
    const int*   mb0 = smk + (size_t)b * S_ * T_;
    const float* tb  = tm  + (size_t)b * T_;
    const int base = g * CPG * TC;

    float accx[5], accm[5];
#pragma unroll
    for (int i = 0; i < 5; i++) { accx[i] = 0.f; accm[i] = 0.f; }
    float cnt = 0.f, tsum = 0.f;

    float4 rxA[5], rxB[5];
    int4   rmA[5], rmB[5];
    float4 tqA, tqB;

    LOADC(rxA, rmA, tqA, base);                        // chunk 0
#pragma unroll
    for (int cc = 0; cc < CPG; cc += 2) {
        LOADC(rxB, rmB, tqB, base + (cc + 1) * TC);    // chunk cc+1 in flight
        PROCC(rxA, rmA, tqA);                          // process chunk cc
        if (cc + 2 < CPG)
            LOADC(rxA, rmA, tqA, base + (cc + 2) * TC); // chunk cc+2 in flight
        PROCC(rxB, rmB, tqB);                          // process chunk cc+1
    }

    // final reductions + writes
#pragma unroll
    for (int i = 0; i < 5; i++) if (i < nb) {
        const float sx = wred(accx[i]);
        const float sm = wred(accm[i]);
        if (lane == 0) {
            const int s = w + 8 * i;
            float* dst = g_px + ((size_t)g * B_ + b) * NF;
            dst[s]      = sx;
            dst[S_ + s] = sm;
        }
    }
    if (w == 0) {
        const float rc = wred(cnt);
        const float rt = wred(tsum);
        if (lane == 0) { g_pm[g * B_ + b] = rc; g_pt[g * B_ + b] = rt; }
    }
}

// ---------------------------------------------------------------------------
// Stage 2: one CTA per batch (128 x 528). Split-K GEMVs with compile-time
// trip counts + unroll so ~8 independent LDG.128 stay in flight per thread.
// ---------------------------------------------------------------------------
__global__ __launch_bounds__(NTHR2, 1) void stage2(
    const float* __restrict__ stat,
    const float* __restrict__ Ws,  const float* __restrict__ bs,
    const float* __restrict__ Wt,  const float* __restrict__ bt,
    const float* __restrict__ Wst, const float* __restrict__ bst,
    const float* __restrict__ Wm,  const float* __restrict__ bm,
    const float* __restrict__ Wc,  const float* __restrict__ bc,
    float* __restrict__ out) {
    __shared__ float xpart[NF][2];
    __shared__ float xsum[NF];
    __shared__ float part[8][MERGED_];
    __shared__ float comb[MERGED_];
    __shared__ float comb2[MERGED_];
    __shared__ float sden[2];

    const int b = blockIdx.x;
    const int tid = threadIdx.x;

    // ---- Phase A: group-partial gather (1 load/thread), den/time, static -
    if (tid < 2 * NF) {
        const int f = tid >> 1, j = tid & 1;
        xpart[f][j] = g_px[((size_t)j * B_ + b) * NF + f];
    } else if (tid == 2 * NF) {
        sden[0] = g_pm[b] + g_pm[B_ + b];
    } else if (tid == 2 * NF + 1) {
        sden[1] = g_pt[b] + g_pt[B_ + b];
    } else if (tid >= 448 && tid < 448 + ST_) {
        const int j = tid - 448;
        float p = bst[j];
#pragma unroll
        for (int i = 0; i < ST_; i++) p += stat[b * ST_ + i] * Wst[i * ST_ + j];
        comb[D_ + j] = p;
    }
    __syncthreads();

    // ---- Phase B: combine xsum partials ----------------------------------
    if (tid < NF)
        xsum[tid] = xpart[tid][0] + xpart[tid][1];
    __syncthreads();

    // ---- Phase C: projection partials (512 thr = 64 quads x 8 ranks) -----
    if (tid < 512) {
        const int d0 = (tid & 63) * 4;
        const int r  = tid >> 6;
        float a0 = 0.f, a1 = 0.f, a2 = 0.f, a3 = 0.f;
#pragma unroll
        for (int i = 0; i < 9; i++) {          // k = r + 8i <= 71, literal
            const int k = r + 8 * i;
            const float4 w = *(const float4*)(Ws + (size_t)k * D_ + d0);
            const float c = xsum[k];
            a0 += c * w.x; a1 += c * w.y; a2 += c * w.z; a3 += c * w.w;
        }
        if (r < 2) {                           // tail k = 72, 73
            const int k = 72 + r;
            const float4 w = *(const float4*)(Ws + (size_t)k * D_ + d0);
            const float c = xsum[k];
            a0 += c * w.x; a1 += c * w.y; a2 += c * w.z; a3 += c * w.w;
        }
        part[r][d0] = a0; part[r][d0 + 1] = a1;
        part[r][d0 + 2] = a2; part[r][d0 + 3] = a3;
    }
    __syncthreads();

    // ---- Phase D: reduce projection, add bias/time terms -----------------
    if (tid < D_) {
        float s = 0.f;
#pragma unroll
        for (int r = 0; r < 8; r++) s += part[r][tid];
        const float den = fmaxf(sden[0], 1e-9f);
        const float tsc = sden[1] / den;
        comb[tid] = s / den + bs[tid] + bt[tid] + tsc * Wt[tid];
    }
    __syncthreads();

    // ---- Phase E: merge partials (528 thr = 66 quads x 8 ranks) ----------
    {
        const int q = tid % 66, r = tid / 66;
        const int n0 = q * 4;
        float a0 = 0.f, a1 = 0.f, a2 = 0.f, a3 = 0.f;
#pragma unroll 8
        for (int i = 0; i < 33; i++) {         // k = r + 8i <= 263, literal
            const int k = r + 8 * i;
            const float4 w = *(const float4*)(Wm + (size_t)k * MERGED_ + n0);
            const float c = comb[k];
            a0 += c * w.x; a1 += c * w.y; a2 += c * w.z; a3 += c * w.w;
        }
        part[r][n0] = a0; part[r][n0 + 1] = a1;
        part[r][n0 + 2] = a2; part[r][n0 + 3] = a3;
    }
    __syncthreads();

    // ---- Phase F: reduce merge, ReLU -------------------------------------
    if (tid < MERGED_) {
        float s = 0.f;
#pragma unroll
        for (int r = 0; r < 8; r++) s += part[r][tid];
        comb2[tid] = fmaxf(s + bm[tid], 0.f);
    }
    __syncthreads();

    // ---- Phase G: classifier (warps 0,1) ---------------------------------
    const int w = tid >> 5, lane = tid & 31;
    if (w < C_) {
        float p = 0.f;
#pragma unroll
        for (int i = lane; i < MERGED_; i += 32) p += comb2[i] * Wc[i * C_ + w];
        p = wred(p);
        if (lane == 0) out[b * C_ + w] = p + bc[w];
    }
}

extern "C" void kernel_launch(void* const* d_in, const int* in_sizes, int n_in,
                              void* d_out, int out_size) {
    const float* x   = (const float*)d_in[0];
    const float* st  = (const float*)d_in[1];
    const float* tm  = (const float*)d_in[2];
    const int*   smk = (const int*)  d_in[3];
    const float* Ws  = (const float*)d_in[4];
    const float* bs  = (const float*)d_in[5];
    const float* Wt  = (const float*)d_in[6];
    const float* bt  = (const float*)d_in[7];
    const float* Wst = (const float*)d_in[8];
    const float* bst = (const float*)d_in[9];
    const float* Wm  = (const float*)d_in[10];
    const float* bm  = (const float*)d_in[11];
    const float* Wc  = (const float*)d_in[12];
    const float* bc  = (const float*)d_in[13];

    stage1<<<dim3(NGRP, B_), 256>>>(x, smk, tm);
    stage2<<<B_, NTHR2>>>(st, Ws, bs, Wt, bt, Wst, bst, Wm, bm, Wc, bc,
                          (float*)d_out);
}